// round 8
// baseline (speedup 1.0000x reference)
#include <cuda_runtime.h>
#include <cstdint>

#define B_  8
#define H_  224
#define W_  224
#define C_  192
#define QT  8        // q positions per block
#define NQ  2        // q per thread
#define PAIRS 32     // channel pairs (threadIdx.x)
#define QTH  4       // q-thread groups (threadIdx.y)
#define NTHREADS 128
#define RH  56       // output rows per block
#define SROW 14      // staged columns per row (QT + 6)
#define STAGES 12
#define STAGE_BYTES (SROW * 64 * 4)          // 3584 B per stage
#define RING_BYTES  (STAGES * STAGE_BYTES)   // 43008 B
#define ROWSZ (W_ * C_)
#define IMGSZ (H_ * W_ * C_)

typedef unsigned long long u64;

__device__ __forceinline__ void fma2(u64 &d, u64 a, u64 b) {
    asm("fma.rn.f32x2 %0, %1, %2, %0;" : "+l"(d) : "l"(a), "l"(b));
}
__device__ __forceinline__ u64 pack2(float lo, float hi) {
    return (u64)__float_as_uint(lo) | ((u64)__float_as_uint(hi) << 32);
}
__device__ __forceinline__ void cpasync16(uint32_t dst, const float* src) {
    asm volatile("cp.async.cg.shared.global [%0], [%1], 16;" :: "r"(dst), "l"(src));
}
__device__ __forceinline__ void cp_commit() {
    asm volatile("cp.async.commit_group;" ::: "memory");
}
__device__ __forceinline__ void cp_wait4() {
    asm volatile("cp.async.wait_group 4;" ::: "memory");
}
__device__ __forceinline__ void cp_wait0() {
    asm volatile("cp.async.wait_group 0;" ::: "memory");
}
__device__ __forceinline__ uint32_t smem_u32(const void* p) {
    uint32_t a;
    asm("{ .reg .u64 t; cvta.to.shared.u64 t, %1; cvt.u32.u64 %0, t; }" : "=r"(a) : "l"(p));
    return a;
}

// Compute half-step at row phase T7 (t % 7), consuming stage at byte offset
// offC (advanced by 1 stage). Kernel rows i in [ILO, IHI] only (wedge prune).
#define STEP_RANGE(T7, ILO, IHI, DOSTORE) do {                                \
    const char* sb = (const char*)sbuf + offC + ty * (NQ * 256) + tx * 8;     \
    u64 w[8];                                                                 \
    _Pragma("unroll")                                                         \
    for (int d = 0; d < 8; ++d)                                               \
        w[d] = *(const u64*)(sb + d * 256);                                   \
    _Pragma("unroll")                                                         \
    for (int i = 0; i < 7; ++i) {                                             \
        if (i >= (ILO) && i <= (IHI)) {                                       \
            const int s = ((T7) + i + 2) % 7;                                 \
            _Pragma("unroll")                                                 \
            for (int j = 0; j < 7; ++j) {                                     \
                const u64 kv = kreg[i * 7 + j];                               \
                fma2(acc[s][0], kv, w[6 - j]);                                \
                fma2(acc[s][1], kv, w[7 - j]);                                \
            }                                                                 \
        }                                                                     \
    }                                                                         \
    {                                                                         \
        const int so = ((T7) + 2) % 7;                                        \
        if (DOSTORE) {                                                        \
            *(u64*)(out + outOff)      = acc[so][0];                          \
            *(u64*)(out + outOff + C_) = acc[so][1];                          \
            outOff += ROWSZ;                                                  \
        }                                                                     \
        acc[so][0] = 0ULL; acc[so][1] = 0ULL;                                 \
    }                                                                         \
    offC += STAGE_BYTES; if (offC >= RING_BYTES) offC -= RING_BYTES;          \
} while (0)

// Macro: 2 rows. Prefetch (distance +8 rows) issued BEFORE wait+sync so it is
// off the critical path; WAR-safe since target stages were last read 4 macros
// ago (>= 3 barriers separation). wait_group 4 = 5 commit groups in flight.
#define MACRO2P(T7a, LOa, STa, T7b, LOb, STb) do {                            \
    {                                                                         \
        const uint32_t dA = sdst + offP;                                      \
        cpasync16(dA, rowPtr + colOff0);                                      \
        if (has1) cpasync16(dA + 2048, rowPtr + colOff1);                     \
        rowPtr += ROWSZ; if (rowPtr >= xEnd) rowPtr -= IMGSZ;                 \
        uint32_t p2 = offP + STAGE_BYTES;                                     \
        if (p2 >= RING_BYTES) p2 -= RING_BYTES;                               \
        const uint32_t dB = sdst + p2;                                        \
        cpasync16(dB, rowPtr + colOff0);                                      \
        if (has1) cpasync16(dB + 2048, rowPtr + colOff1);                     \
        rowPtr += ROWSZ; if (rowPtr >= xEnd) rowPtr -= IMGSZ;                 \
        cp_commit();                                                          \
        offP += 2 * STAGE_BYTES; if (offP >= RING_BYTES) offP -= RING_BYTES;  \
    }                                                                         \
    cp_wait4();                                                               \
    __syncthreads();                                                          \
    STEP_RANGE(T7a, LOa, 6, STa);                                             \
    STEP_RANGE(T7b, LOb, 6, STb);                                             \
} while (0)

// 7 main macros = 14 rows (acc phase period). Starts at t%7 == 6.
#define GROUP7M()                                                             \
    MACRO2P(6, 0, 1, 0, 0, 1); MACRO2P(1, 0, 1, 2, 0, 1);                     \
    MACRO2P(3, 0, 1, 4, 0, 1); MACRO2P(5, 0, 1, 6, 0, 1);                     \
    MACRO2P(0, 0, 1, 1, 0, 1); MACRO2P(2, 0, 1, 3, 0, 1);                     \
    MACRO2P(4, 0, 1, 5, 0, 1)

__global__ void __launch_bounds__(NTHREADS, 3)
dwconv_pipe4(const float* __restrict__ x, const float* __restrict__ kern,
             float* __restrict__ out)
{
    __shared__ float sbuf[STAGES][SROW][64];   // 43,008 B (12-stage ring)

    const int tx  = threadIdx.x;           // channel pair 0..31
    const int ty  = threadIdx.y;           // q group 0..3
    const int tid = ty * PAIRS + tx;

    const int wt = blockIdx.x;              // 0..27
    const int ht = blockIdx.y;              // 0..3
    const int bz = blockIdx.z;              // 0..23
    const int b  = bz / 3;
    const int g  = bz % 3;

    const int qbase = wt * QT;
    const int p0    = ht * RH;              // p0 % 7 == 0
    const int cbase = g * 64;
    const int c0    = cbase + 2 * tx;

    // ---- 49 kernel taps for this channel pair -> registers (f32x2) ----
    u64 kreg[49];
    #pragma unroll
    for (int t = 0; t < 49; ++t)
        kreg[t] = pack2(kern[c0 * 49 + t], kern[(c0 + 1) * 49 + t]);

    // ---- cp.async staging plan: 224 float4 per stage, threads 0..95 take 2 ----
    const int s0 = tid >> 4, v0 = tid & 15;             // cols 0..7
    const bool has1 = tid < 96;
    const int s1 = (tid + 128) >> 4;                    // cols 8..13
    int qg0 = qbase - 3 + s0; qg0 += (qg0 < 0) ? W_ : 0; qg0 -= (qg0 >= W_) ? W_ : 0;
    int qg1 = qbase - 3 + s1; qg1 += (qg1 < 0) ? W_ : 0; qg1 -= (qg1 >= W_) ? W_ : 0;
    const int colOff0 = qg0 * C_ + cbase + v0 * 4;
    const int colOff1 = qg1 * C_ + cbase + v0 * 4;
    const uint32_t sdst = smem_u32(&sbuf[0][0][0]) + (uint32_t)(s0 * 256 + v0 * 16);

    // row cursor (circular over H, pointer-only)
    const float* const xBase = x + b * IMGSZ;
    const float* const xEnd  = xBase + IMGSZ;
    const float* rowPtr = xBase + (p0 - 3 < 0 ? p0 - 3 + H_ : p0 - 3) * ROWSZ;

    // ---- prologue: stage rows 0..7 into stages 0..7 (4 groups of 2 rows) ----
    #pragma unroll
    for (int pr = 0; pr < 4; ++pr) {
        uint32_t dA = sdst + (2 * pr) * STAGE_BYTES;
        cpasync16(dA, rowPtr + colOff0);
        if (has1) cpasync16(dA + 2048, rowPtr + colOff1);
        rowPtr += ROWSZ; if (rowPtr >= xEnd) rowPtr -= IMGSZ;
        uint32_t dB = sdst + (2 * pr + 1) * STAGE_BYTES;
        cpasync16(dB, rowPtr + colOff0);
        if (has1) cpasync16(dB + 2048, rowPtr + colOff1);
        rowPtr += ROWSZ; if (rowPtr >= xEnd) rowPtr -= IMGSZ;
        cp_commit();
    }

    uint32_t offC = 0;                      // consume cursor (1 stage per row)
    uint32_t offP = 8 * STAGE_BYTES;        // prefetch cursor (+8 rows ahead)

    // 7 rolling accumulators (static slots), f32x2 x NQ
    u64 acc[7][2];
    #pragma unroll
    for (int m = 0; m < 7; ++m) { acc[m][0] = 0ULL; acc[m][1] = 0ULL; }

    const int qOut = qbase + ty * NQ;
    int outOff = ((b * H_ + p0) * W_ + qOut) * C_ + c0;

    // ---- warm-up: rows 0..5, wedge-pruned (i >= 6-t), no stores ----
    MACRO2P(0, 6, 0, 1, 5, 0);
    MACRO2P(2, 4, 0, 3, 3, 0);
    MACRO2P(4, 2, 0, 5, 1, 0);

    // ---- main: rows 6..47, three 7-macro groups (I$-resident) ----
    #pragma unroll 1
    for (int o = 0; o < 3; ++o) {
        GROUP7M();
    }
    // ---- main remainder: rows 48..55 ----
    MACRO2P(6, 0, 1, 0, 0, 1);
    MACRO2P(1, 0, 1, 2, 0, 1);
    MACRO2P(3, 0, 1, 4, 0, 1);
    MACRO2P(5, 0, 1, 6, 0, 1);

    // ---- tail: rows 56..61, wedge-pruned (i <= 61-t), all data resident ----
    cp_wait0();
    __syncthreads();
    STEP_RANGE(0, 0, 5, 1);
    STEP_RANGE(1, 0, 4, 1);
    STEP_RANGE(2, 0, 3, 1);
    STEP_RANGE(3, 0, 2, 1);
    STEP_RANGE(4, 0, 1, 1);
    STEP_RANGE(5, 0, 0, 1);
}

extern "C" void kernel_launch(void* const* d_in, const int* in_sizes, int n_in,
                              void* d_out, int out_size) {
    const float* x    = (const float*)d_in[0];   // (8,224,224,192) fp32
    const float* kern = (const float*)d_in[1];   // (192,7,7) fp32
    float* out        = (float*)d_out;           // (8,224,224,192) fp32

    dim3 grid(W_ / QT, H_ / RH, B_ * 3);  // 28 x 4 x 24 = 2688 blocks
    dim3 block(PAIRS, QTH, 1);            // 128 threads
    dwconv_pipe4<<<grid, block>>>(x, kern, out);
}